// round 3
// baseline (speedup 1.0000x reference)
#include <cuda_runtime.h>
#include <cuda_bf16.h>
#include <math.h>

#define NN 100000
#define EE 1600000
#define F_IN 128
#define HID 64
#define HEADS 8
#define KORD 14
#define NGRAPH 128
#define NCLS 10

// ---------------- scratch (static device globals; no allocs allowed) ----------------
__device__ float g_Y  [NN * HID];
__device__ float g_T0 [NN * HID];
__device__ float g_T1 [NN * HID];
__device__ float g_OUT[NN * HID];
__device__ int   g_count [NN];
__device__ int   g_cursor[NN];
__device__ int   g_rowptr[NN + 1];
__device__ float g_dinv  [NN];
__device__ int   g_ecol[EE];
__device__ float g_eval[EE];
__device__ float g_coeff[3 * KORD];
__device__ float g_psum[NGRAPH * HID];
__device__ float g_pcnt[NGRAPH];

// ---------------- small setup kernels ----------------
__global__ void __launch_bounds__(256) zero_kernel(int* cnt, int* cur, float* ps, float* pc) {
    int i = blockIdx.x * blockDim.x + threadIdx.x;
    if (i < NN) { cnt[i] = 0; cur[i] = 0; }
    if (i < NGRAPH * HID) ps[i] = 0.f;
    if (i < NGRAPH) pc[i] = 0.f;
}

__global__ void __launch_bounds__(64) coeff_kernel(const float* __restrict__ th1,
                             const float* __restrict__ ths,
                             float* __restrict__ gc) {
    int i = threadIdx.x;
    if (i >= 3 * KORD) return;
    int layer = i / KORD, k = i % KORD;
    const float* src = (layer == 0) ? th1 : (ths + (layer - 1) * HEADS * KORD);
    float s = 0.f;
    #pragma unroll
    for (int h = 0; h < HEADS; ++h) s += src[h * KORD + k];
    gc[i] = s * (1.0f / HEADS);
}

__global__ void __launch_bounds__(256) degree_kernel(const int* __restrict__ row, int* __restrict__ cnt) {
    int e = blockIdx.x * blockDim.x + threadIdx.x;
    if (e < EE) atomicAdd(&cnt[row[e]], 1);
}

__global__ void __launch_bounds__(256) dinv_kernel(const int* __restrict__ cnt, float* __restrict__ dinv) {
    int n = blockIdx.x * blockDim.x + threadIdx.x;
    if (n < NN) dinv[n] = rsqrtf(fmaxf((float)cnt[n], 1.0f));
}

// single-block exclusive scan over counts -> rowptr (N=100000, 1024 threads)
__global__ void __launch_bounds__(1024) scan_kernel(const int* __restrict__ cnt, int* __restrict__ rowptr) {
    __shared__ int sums[1024];
    const int CH = (NN + 1023) / 1024;  // 98
    int tid = threadIdx.x;
    int base = tid * CH;
    int s = 0;
    #pragma unroll 1
    for (int i = 0; i < CH; ++i) {
        int idx = base + i;
        if (idx < NN) s += cnt[idx];
    }
    sums[tid] = s;
    __syncthreads();
    // Hillis-Steele inclusive scan
    #pragma unroll 1
    for (int off = 1; off < 1024; off <<= 1) {
        int v = (tid >= off) ? sums[tid - off] : 0;
        __syncthreads();
        sums[tid] += v;
        __syncthreads();
    }
    int run = (tid == 0) ? 0 : sums[tid - 1];  // exclusive prefix of this chunk
    #pragma unroll 1
    for (int i = 0; i < CH; ++i) {
        int idx = base + i;
        if (idx < NN) { rowptr[idx] = run; run += cnt[idx]; }
    }
    if (tid == 1023) rowptr[NN] = run;  // == EE
}

__global__ void __launch_bounds__(256) scatter_kernel(const int* __restrict__ row, const int* __restrict__ col,
                               const float* __restrict__ dinv,
                               const int* __restrict__ rowptr, int* __restrict__ cursor,
                               int* __restrict__ ecol, float* __restrict__ eval) {
    int e = blockIdx.x * blockDim.x + threadIdx.x;
    if (e >= EE) return;
    int r = row[e], c = col[e];
    int p = rowptr[r] + atomicAdd(&cursor[r], 1);
    ecol[p] = c;
    eval[p] = dinv[r] * dinv[c];
}

// ---------------- dense y = h @ W  (F = 128 or 64, out width 64) ----------------
template <int F>
__global__ void __launch_bounds__(256) gemm_kernel(const float* __restrict__ x, const float* __restrict__ W,
                            float* __restrict__ y) {
    __shared__ float sW[F * HID];
    int t = threadIdx.x;  // 256
    for (int i = t; i < F * HID; i += 256) sW[i] = W[i];
    __syncthreads();
    int rbase = blockIdx.x * 64;
    int c  = t & 63;
    int rg = t >> 6;  // 0..3
    float acc[16];
    #pragma unroll
    for (int i = 0; i < 16; ++i) acc[i] = 0.f;
    #pragma unroll 1
    for (int k = 0; k < F; ++k) {
        float w = sW[k * HID + c];
        #pragma unroll
        for (int i = 0; i < 16; ++i) {
            int r = rbase + rg + 4 * i;
            r = (r < NN) ? r : (NN - 1);
            acc[i] += x[(size_t)r * F + k] * w;
        }
    }
    #pragma unroll
    for (int i = 0; i < 16; ++i) {
        int r = rbase + rg + 4 * i;
        if (r < NN) y[(size_t)r * HID + c] = acc[i];
    }
}

// ---------------- sparse prop: one warp per node, CSR ----------------
// MODE 0: t = prop(in);  tnext = t;  out = coeff[0]*in[row] + coeff[1]*t
// MODE 1: t = 2*prop(in) - tprev[row];  tnext = t;  out += coeff[kidx]*t
template <int MODE>
__global__ void __launch_bounds__(256) prop_kernel(const float* __restrict__ in, const float* __restrict__ tprev,
                            float* __restrict__ tnext, float* __restrict__ out,
                            const float* __restrict__ coeff, int kidx,
                            const int* __restrict__ rowptr, const int* __restrict__ ecol,
                            const float* __restrict__ eval) {
    int warp = (blockIdx.x * blockDim.x + threadIdx.x) >> 5;
    int lane = threadIdx.x & 31;
    if (warp >= NN) return;
    int start = rowptr[warp];
    int end   = rowptr[warp + 1];
    float acc0 = 0.f, acc1 = 0.f;
    for (int e = start; e < end; e += 32) {
        int   myc = 0;
        float myv = 0.f;
        int idx = e + lane;
        if (idx < end) { myc = ecol[idx]; myv = eval[idx]; }
        int cnt = min(32, end - e);
        for (int j = 0; j < cnt; ++j) {
            int   c = __shfl_sync(0xffffffffu, myc, j);
            float v = __shfl_sync(0xffffffffu, myv, j);
            const float* p = in + (size_t)c * HID + lane;
            acc0 += v * p[0];
            acc1 += v * p[32];
        }
    }
    acc0 = -acc0;
    acc1 = -acc1;
    size_t o = (size_t)warp * HID + lane;
    float ck = coeff[kidx];
    if (MODE == 0) {
        float c0 = coeff[0];
        tnext[o]      = acc0;
        tnext[o + 32] = acc1;
        out[o]      = c0 * in[o]      + ck * acc0;
        out[o + 32] = c0 * in[o + 32] + ck * acc1;
    } else {
        float t0 = 2.f * acc0 - tprev[o];
        float t1 = 2.f * acc1 - tprev[o + 32];
        tnext[o]      = t0;
        tnext[o + 32] = t1;
        out[o]      += ck * t0;
        out[o + 32] += ck * t1;
    }
}

__global__ void __launch_bounds__(256) bias_relu_kernel(float* __restrict__ h, const float* __restrict__ b) {
    int i = blockIdx.x * blockDim.x + threadIdx.x;
    if (i < NN * HID) {
        float v = h[i] + b[i & (HID - 1)];
        h[i] = fmaxf(v, 0.f);
    }
}

// ---------------- pooling (batch sorted -> run-length compressed atomics) ----------------
__global__ void __launch_bounds__(256) pool_kernel(const float* __restrict__ h, const int* __restrict__ batch,
                            float* __restrict__ sums, float* __restrict__ cnts) {
    const int NCHUNK = (NN + 7) / 8;  // 12500
    int t = blockIdx.x * blockDim.x + threadIdx.x;
    if (t >= NCHUNK * HID) return;
    int f = t & 63;
    int chunk = t >> 6;
    int n0 = chunk * 8;
    int cur = -1;
    float acc = 0.f;
    #pragma unroll 1
    for (int i = 0; i < 8; ++i) {
        int n = n0 + i;
        if (n >= NN) break;
        int b = batch[n];
        if (b != cur) {
            if (cur >= 0) atomicAdd(&sums[cur * HID + f], acc);
            cur = b; acc = 0.f;
        }
        acc += h[(size_t)n * HID + f];
    }
    if (cur >= 0) atomicAdd(&sums[cur * HID + f], acc);
    if (f == 0) {
        cur = -1;
        float c = 0.f;
        #pragma unroll 1
        for (int i = 0; i < 8; ++i) {
            int n = n0 + i;
            if (n >= NN) break;
            int b = batch[n];
            if (b != cur) {
                if (cur >= 0) atomicAdd(&cnts[cur], c);
                cur = b; c = 0.f;
            }
            c += 1.f;
        }
        if (cur >= 0) atomicAdd(&cnts[cur], c);
    }
}

// ---------------- final MLP + log-softmax (one block, one thread per graph) ------------
__global__ void __launch_bounds__(128) mlp_kernel(const float* __restrict__ sums, const float* __restrict__ cnts,
                           const float* __restrict__ w1, const float* __restrict__ b1v,
                           const float* __restrict__ w2, const float* __restrict__ b2v,
                           float* __restrict__ out) {
    __shared__ float sw1[HID * HID];
    __shared__ float sb1[HID];
    __shared__ float sw2[HID * NCLS];
    __shared__ float sb2[NCLS];
    int t = threadIdx.x;
    for (int i = t; i < HID * HID; i += 128) sw1[i] = w1[i];
    for (int i = t; i < HID * NCLS; i += 128) sw2[i] = w2[i];
    if (t < HID)  sb1[t] = b1v[t];
    if (t < NCLS) sb2[t] = b2v[t];
    __syncthreads();
    if (t >= NGRAPH) return;
    float inv = 1.0f / fmaxf(cnts[t], 1.0f);
    float g[HID];
    #pragma unroll 1
    for (int i = 0; i < HID; ++i) g[i] = sums[t * HID + i] * inv;
    float hh[HID];
    #pragma unroll 1
    for (int c = 0; c < HID; ++c) {
        float s = sb1[c];
        #pragma unroll
        for (int k = 0; k < HID; ++k) s += g[k] * sw1[k * HID + c];
        hh[c] = fmaxf(s, 0.f);
    }
    float lg[NCLS];
    float mx = -1e30f;
    #pragma unroll 1
    for (int c = 0; c < NCLS; ++c) {
        float s = sb2[c];
        #pragma unroll
        for (int k = 0; k < HID; ++k) s += hh[k] * sw2[k * NCLS + c];
        lg[c] = s;
        mx = fmaxf(mx, s);
    }
    float se = 0.f;
    #pragma unroll 1
    for (int c = 0; c < NCLS; ++c) se += expf(lg[c] - mx);
    float lse = mx + logf(se);
    #pragma unroll 1
    for (int c = 0; c < NCLS; ++c) out[t * NCLS + c] = lg[c] - lse;
}

// ---------------- launch ----------------
extern "C" void kernel_launch(void* const* d_in, const int* in_sizes, int n_in,
                              void* d_out, int out_size) {
    const float* x      = (const float*)d_in[0];
    const int*   ei     = (const int*)  d_in[1];
    const int*   batch  = (const int*)  d_in[2];
    const float* W1     = (const float*)d_in[3];
    const float* theta1 = (const float*)d_in[4];
    const float* b1     = (const float*)d_in[5];
    const float* Ws     = (const float*)d_in[6];
    const float* thetas = (const float*)d_in[7];
    const float* bs     = (const float*)d_in[8];
    const float* lin1w  = (const float*)d_in[9];
    const float* lin1b  = (const float*)d_in[10];
    const float* lin2w  = (const float*)d_in[11];
    const float* lin2b  = (const float*)d_in[12];
    float* out = (float*)d_out;

    const int* row = ei;
    const int* col = ei + EE;

    float *Y, *T0, *T1, *OUT, *dinv, *eval, *coeff, *psum, *pcnt;
    int *cnt, *cur, *rowptr, *ecol;
    cudaGetSymbolAddress((void**)&Y,      g_Y);
    cudaGetSymbolAddress((void**)&T0,     g_T0);
    cudaGetSymbolAddress((void**)&T1,     g_T1);
    cudaGetSymbolAddress((void**)&OUT,    g_OUT);
    cudaGetSymbolAddress((void**)&dinv,   g_dinv);
    cudaGetSymbolAddress((void**)&eval,   g_eval);
    cudaGetSymbolAddress((void**)&coeff,  g_coeff);
    cudaGetSymbolAddress((void**)&psum,   g_psum);
    cudaGetSymbolAddress((void**)&pcnt,   g_pcnt);
    cudaGetSymbolAddress((void**)&cnt,    g_count);
    cudaGetSymbolAddress((void**)&cur,    g_cursor);
    cudaGetSymbolAddress((void**)&rowptr, g_rowptr);
    cudaGetSymbolAddress((void**)&ecol,   g_ecol);

    // setup
    zero_kernel<<<(NN + 255) / 256, 256>>>(cnt, cur, psum, pcnt);
    coeff_kernel<<<1, 64>>>(theta1, thetas, coeff);
    degree_kernel<<<(EE + 255) / 256, 256>>>(row, cnt);
    dinv_kernel<<<(NN + 255) / 256, 256>>>(cnt, dinv);
    scan_kernel<<<1, 1024>>>(cnt, rowptr);
    scatter_kernel<<<(EE + 255) / 256, 256>>>(row, col, dinv, rowptr, cur, ecol, eval);

    const int PROP_BLOCKS = (NN * 32 + 255) / 256;
    float* ring[3] = {Y, T0, T1};

    for (int layer = 0; layer < 3; ++layer) {
        // y = h @ W
        if (layer == 0) {
            gemm_kernel<F_IN><<<(NN + 63) / 64, 256>>>(x, W1, Y);
        } else {
            gemm_kernel<HID><<<(NN + 63) / 64, 256>>>(OUT, Ws + (size_t)(layer - 1) * HID * HID, Y);
        }
        const float* lc = coeff + layer * KORD;
        // t_cur = prop(y); out = c0*y + c1*t_cur
        prop_kernel<0><<<PROP_BLOCKS, 256>>>(Y, nullptr, T0, OUT, lc, 1, rowptr, ecol, eval);
        // Chebyshev recursion
        for (int k = 2; k < KORD; ++k) {
            float* curb  = ring[(k - 1) % 3];
            float* prevb = ring[(k - 2) % 3];
            float* nextb = ring[k % 3];
            prop_kernel<1><<<PROP_BLOCKS, 256>>>(curb, prevb, nextb, OUT, lc, k, rowptr, ecol, eval);
        }
        const float* bptr = (layer == 0) ? b1 : (bs + (size_t)(layer - 1) * HID);
        bias_relu_kernel<<<(NN * HID + 255) / 256, 256>>>(OUT, bptr);
    }

    // global mean pool + MLP + log_softmax
    const int NCHUNK = (NN + 7) / 8;
    pool_kernel<<<(NCHUNK * HID + 255) / 256, 256>>>(OUT, batch, psum, pcnt);
    mlp_kernel<<<1, 128>>>(psum, pcnt, lin1w, lin1b, lin2w, lin2b, out);
}

// round 5
// speedup vs baseline: 1.2303x; 1.2303x over previous
#include <cuda_runtime.h>
#include <cuda_fp16.h>
#include <math.h>

#define NN 100000
#define EE 1600000
#define F_IN 128
#define HID 64
#define HEADS 8
#define KORD 14
#define NGRAPH 128
#define NCLS 10

// ---------------- scratch (static device globals; no allocs allowed) ----------------
__device__ __half g_Yh [NN * HID];   // iterate ring (fp16)
__device__ __half g_T0h[NN * HID];
__device__ __half g_T1h[NN * HID];
__device__ float  g_OUT[NN * HID];   // per-layer Chebyshev accumulator (fp32)
__device__ int    g_count [NN];
__device__ int    g_cursor[NN];
__device__ int    g_rowptr[NN + 1];
__device__ float  g_dinv  [NN];
__device__ int    g_ecol[EE];
__device__ float  g_eval[EE];
__device__ float  g_coeff[3 * KORD];
__device__ float  g_psum[NGRAPH * HID];
__device__ float  g_pcnt[NGRAPH];

// ---------------- small setup kernels ----------------
__global__ void __launch_bounds__(256) zero_kernel(int* cnt, int* cur, float* ps, float* pc) {
    int i = blockIdx.x * blockDim.x + threadIdx.x;
    if (i < NN) { cnt[i] = 0; cur[i] = 0; }
    if (i < NGRAPH * HID) ps[i] = 0.f;
    if (i < NGRAPH) pc[i] = 0.f;
}

__global__ void __launch_bounds__(64) coeff_kernel(const float* __restrict__ th1,
                             const float* __restrict__ ths,
                             float* __restrict__ gc) {
    int i = threadIdx.x;
    if (i >= 3 * KORD) return;
    int layer = i / KORD, k = i % KORD;
    const float* src = (layer == 0) ? th1 : (ths + (layer - 1) * HEADS * KORD);
    float s = 0.f;
    #pragma unroll
    for (int h = 0; h < HEADS; ++h) s += src[h * KORD + k];
    gc[i] = s * (1.0f / HEADS);
}

__global__ void __launch_bounds__(256) degree_kernel(const int* __restrict__ row, int* __restrict__ cnt) {
    int e = blockIdx.x * blockDim.x + threadIdx.x;
    if (e < EE) atomicAdd(&cnt[row[e]], 1);
}

__global__ void __launch_bounds__(256) dinv_kernel(const int* __restrict__ cnt, float* __restrict__ dinv) {
    int n = blockIdx.x * blockDim.x + threadIdx.x;
    if (n < NN) dinv[n] = rsqrtf(fmaxf((float)cnt[n], 1.0f));
}

// single-block exclusive scan over counts -> rowptr (N=100000, 1024 threads)
__global__ void __launch_bounds__(1024) scan_kernel(const int* __restrict__ cnt, int* __restrict__ rowptr) {
    __shared__ int sums[1024];
    const int CH = (NN + 1023) / 1024;  // 98
    int tid = threadIdx.x;
    int base = tid * CH;
    int s = 0;
    #pragma unroll 1
    for (int i = 0; i < CH; ++i) {
        int idx = base + i;
        if (idx < NN) s += cnt[idx];
    }
    sums[tid] = s;
    __syncthreads();
    #pragma unroll 1
    for (int off = 1; off < 1024; off <<= 1) {
        int v = (tid >= off) ? sums[tid - off] : 0;
        __syncthreads();
        sums[tid] += v;
        __syncthreads();
    }
    int run = (tid == 0) ? 0 : sums[tid - 1];
    #pragma unroll 1
    for (int i = 0; i < CH; ++i) {
        int idx = base + i;
        if (idx < NN) { rowptr[idx] = run; run += cnt[idx]; }
    }
    if (tid == 1023) rowptr[NN] = run;
}

__global__ void __launch_bounds__(256) scatter_kernel(const int* __restrict__ row, const int* __restrict__ col,
                               const float* __restrict__ dinv,
                               const int* __restrict__ rowptr, int* __restrict__ cursor,
                               int* __restrict__ ecol, float* __restrict__ eval) {
    int e = blockIdx.x * blockDim.x + threadIdx.x;
    if (e >= EE) return;
    int r = row[e], c = col[e];
    int p = rowptr[r] + atomicAdd(&cursor[r], 1);
    ecol[p] = c;
    eval[p] = dinv[r] * dinv[c];
}

// ---------------- dense y = h @ W  (F = 128 or 64, out width 64, fp16 out) ----------------
template <int F>
__global__ void __launch_bounds__(256) gemm_kernel(const float* __restrict__ x, const float* __restrict__ W,
                            __half* __restrict__ y) {
    __shared__ float sW[F * HID];
    int t = threadIdx.x;  // 256
    for (int i = t; i < F * HID; i += 256) sW[i] = W[i];
    __syncthreads();
    int rbase = blockIdx.x * 64;
    int c  = t & 63;
    int rg = t >> 6;  // 0..3
    float acc[16];
    #pragma unroll
    for (int i = 0; i < 16; ++i) acc[i] = 0.f;
    #pragma unroll 1
    for (int k = 0; k < F; ++k) {
        float w = sW[k * HID + c];
        #pragma unroll
        for (int i = 0; i < 16; ++i) {
            int r = rbase + rg + 4 * i;
            r = (r < NN) ? r : (NN - 1);
            acc[i] += x[(size_t)r * F + k] * w;
        }
    }
    #pragma unroll
    for (int i = 0; i < 16; ++i) {
        int r = rbase + rg + 4 * i;
        if (r < NN) y[(size_t)r * HID + c] = __float2half(acc[i]);
    }
}

// ---------------- sparse prop: one warp per node, CSR, fp16 gather ----------------
// lane l owns features {2l, 2l+1} (one half2 / float2 per lane)
// MODE 0: t = -gather(in);          tnext = t;  out  = c0*in[row] + ck*t
// MODE 1: t = -2*gather(in) - prev; tnext = t;  out += ck*t
// MODE 2: t = -2*gather(in) - prev; out = relu(out + ck*t + bias)   (no tnext)
template <int MODE>
__global__ void __launch_bounds__(256) prop_kernel(const __half* __restrict__ in, const __half* __restrict__ tprev,
                            __half* __restrict__ tnext, float* __restrict__ out,
                            const float* __restrict__ coeff, int kidx,
                            const int* __restrict__ rowptr, const int* __restrict__ ecol,
                            const float* __restrict__ eval, const float* __restrict__ bias) {
    int warp = (blockIdx.x * blockDim.x + threadIdx.x) >> 5;
    int lane = threadIdx.x & 31;
    if (warp >= NN) return;
    int start = rowptr[warp];
    int end   = rowptr[warp + 1];
    float acc0 = 0.f, acc1 = 0.f;
    for (int e = start; e < end; e += 32) {
        int   myc = 0;
        float myv = 0.f;
        int idx = e + lane;
        if (idx < end) { myc = ecol[idx]; myv = eval[idx]; }
        int cnt = min(32, end - e);
        for (int j = 0; j < cnt; ++j) {
            int   c = __shfl_sync(0xffffffffu, myc, j);
            float v = __shfl_sync(0xffffffffu, myv, j);
            const __half2* p = reinterpret_cast<const __half2*>(in + (size_t)c * HID);
            float2 f = __half22float2(p[lane]);
            acc0 += v * f.x;
            acc1 += v * f.y;
        }
    }
    size_t o2 = (size_t)warp * 32 + lane;            // half2 index
    float2* outp = reinterpret_cast<float2*>(out) + o2;
    float ck = coeff[kidx];
    if (MODE == 0) {
        float t0 = -acc0, t1 = -acc1;
        float c0 = coeff[0];
        float2 yv = __half22float2(reinterpret_cast<const __half2*>(in)[o2]);
        reinterpret_cast<__half2*>(tnext)[o2] = __floats2half2_rn(t0, t1);
        float2 ov;
        ov.x = c0 * yv.x + ck * t0;
        ov.y = c0 * yv.y + ck * t1;
        *outp = ov;
    } else if (MODE == 1) {
        float2 pv = __half22float2(reinterpret_cast<const __half2*>(tprev)[o2]);
        float t0 = -2.f * acc0 - pv.x;
        float t1 = -2.f * acc1 - pv.y;
        reinterpret_cast<__half2*>(tnext)[o2] = __floats2half2_rn(t0, t1);
        float2 ov = *outp;
        ov.x += ck * t0;
        ov.y += ck * t1;
        *outp = ov;
    } else {
        float2 pv = __half22float2(reinterpret_cast<const __half2*>(tprev)[o2]);
        float t0 = -2.f * acc0 - pv.x;
        float t1 = -2.f * acc1 - pv.y;
        float2 ov = *outp;
        ov.x = fmaxf(ov.x + ck * t0 + bias[2 * lane],     0.f);
        ov.y = fmaxf(ov.y + ck * t1 + bias[2 * lane + 1], 0.f);
        *outp = ov;
    }
}

// ---------------- pooling (batch sorted -> run-length compressed atomics) ----------------
__global__ void __launch_bounds__(256) pool_kernel(const float* __restrict__ h, const int* __restrict__ batch,
                            float* __restrict__ sums, float* __restrict__ cnts) {
    const int NCHUNK = (NN + 7) / 8;  // 12500
    int t = blockIdx.x * blockDim.x + threadIdx.x;
    if (t >= NCHUNK * HID) return;
    int f = t & 63;
    int chunk = t >> 6;
    int n0 = chunk * 8;
    int cur = -1;
    float acc = 0.f;
    #pragma unroll 1
    for (int i = 0; i < 8; ++i) {
        int n = n0 + i;
        if (n >= NN) break;
        int b = batch[n];
        if (b != cur) {
            if (cur >= 0) atomicAdd(&sums[cur * HID + f], acc);
            cur = b; acc = 0.f;
        }
        acc += h[(size_t)n * HID + f];
    }
    if (cur >= 0) atomicAdd(&sums[cur * HID + f], acc);
    if (f == 0) {
        cur = -1;
        float c = 0.f;
        #pragma unroll 1
        for (int i = 0; i < 8; ++i) {
            int n = n0 + i;
            if (n >= NN) break;
            int b = batch[n];
            if (b != cur) {
                if (cur >= 0) atomicAdd(&cnts[cur], c);
                cur = b; c = 0.f;
            }
            c += 1.f;
        }
        if (cur >= 0) atomicAdd(&cnts[cur], c);
    }
}

// ---------------- final MLP + log-softmax (one block, one thread per graph) ------------
__global__ void __launch_bounds__(128) mlp_kernel(const float* __restrict__ sums, const float* __restrict__ cnts,
                           const float* __restrict__ w1, const float* __restrict__ b1v,
                           const float* __restrict__ w2, const float* __restrict__ b2v,
                           float* __restrict__ out) {
    __shared__ float sw1[HID * HID];
    __shared__ float sb1[HID];
    __shared__ float sw2[HID * NCLS];
    __shared__ float sb2[NCLS];
    int t = threadIdx.x;
    for (int i = t; i < HID * HID; i += 128) sw1[i] = w1[i];
    for (int i = t; i < HID * NCLS; i += 128) sw2[i] = w2[i];
    if (t < HID)  sb1[t] = b1v[t];
    if (t < NCLS) sb2[t] = b2v[t];
    __syncthreads();
    if (t >= NGRAPH) return;
    float inv = 1.0f / fmaxf(cnts[t], 1.0f);
    float g[HID];
    #pragma unroll 1
    for (int i = 0; i < HID; ++i) g[i] = sums[t * HID + i] * inv;
    float hh[HID];
    #pragma unroll 1
    for (int c = 0; c < HID; ++c) {
        float s = sb1[c];
        #pragma unroll
        for (int k = 0; k < HID; ++k) s += g[k] * sw1[k * HID + c];
        hh[c] = fmaxf(s, 0.f);
    }
    float lg[NCLS];
    float mx = -1e30f;
    #pragma unroll 1
    for (int c = 0; c < NCLS; ++c) {
        float s = sb2[c];
        #pragma unroll
        for (int k = 0; k < HID; ++k) s += hh[k] * sw2[k * NCLS + c];
        lg[c] = s;
        mx = fmaxf(mx, s);
    }
    float se = 0.f;
    #pragma unroll 1
    for (int c = 0; c < NCLS; ++c) se += expf(lg[c] - mx);
    float lse = mx + logf(se);
    #pragma unroll 1
    for (int c = 0; c < NCLS; ++c) out[t * NCLS + c] = lg[c] - lse;
}

// ---------------- launch ----------------
extern "C" void kernel_launch(void* const* d_in, const int* in_sizes, int n_in,
                              void* d_out, int out_size) {
    const float* x      = (const float*)d_in[0];
    const int*   ei     = (const int*)  d_in[1];
    const int*   batch  = (const int*)  d_in[2];
    const float* W1     = (const float*)d_in[3];
    const float* theta1 = (const float*)d_in[4];
    const float* b1     = (const float*)d_in[5];
    const float* Ws     = (const float*)d_in[6];
    const float* thetas = (const float*)d_in[7];
    const float* bs     = (const float*)d_in[8];
    const float* lin1w  = (const float*)d_in[9];
    const float* lin1b  = (const float*)d_in[10];
    const float* lin2w  = (const float*)d_in[11];
    const float* lin2b  = (const float*)d_in[12];
    float* out = (float*)d_out;

    const int* row = ei;
    const int* col = ei + EE;

    __half *Yh, *T0h, *T1h;
    float *OUT, *dinv, *eval, *coeff, *psum, *pcnt;
    int *cnt, *cur, *rowptr, *ecol;
    cudaGetSymbolAddress((void**)&Yh,     g_Yh);
    cudaGetSymbolAddress((void**)&T0h,    g_T0h);
    cudaGetSymbolAddress((void**)&T1h,    g_T1h);
    cudaGetSymbolAddress((void**)&OUT,    g_OUT);
    cudaGetSymbolAddress((void**)&dinv,   g_dinv);
    cudaGetSymbolAddress((void**)&eval,   g_eval);
    cudaGetSymbolAddress((void**)&coeff,  g_coeff);
    cudaGetSymbolAddress((void**)&psum,   g_psum);
    cudaGetSymbolAddress((void**)&pcnt,   g_pcnt);
    cudaGetSymbolAddress((void**)&cnt,    g_count);
    cudaGetSymbolAddress((void**)&cur,    g_cursor);
    cudaGetSymbolAddress((void**)&rowptr, g_rowptr);
    cudaGetSymbolAddress((void**)&ecol,   g_ecol);

    // setup
    zero_kernel<<<(NN + 255) / 256, 256>>>(cnt, cur, psum, pcnt);
    coeff_kernel<<<1, 64>>>(theta1, thetas, coeff);
    degree_kernel<<<(EE + 255) / 256, 256>>>(row, cnt);
    dinv_kernel<<<(NN + 255) / 256, 256>>>(cnt, dinv);
    scan_kernel<<<1, 1024>>>(cnt, rowptr);
    scatter_kernel<<<(EE + 255) / 256, 256>>>(row, col, dinv, rowptr, cur, ecol, eval);

    const int PROP_BLOCKS = (NN * 32 + 255) / 256;
    __half* ring[3] = {Yh, T0h, T1h};

    for (int layer = 0; layer < 3; ++layer) {
        // y = h @ W  (fp16 output)
        if (layer == 0) {
            gemm_kernel<F_IN><<<(NN + 63) / 64, 256>>>(x, W1, Yh);
        } else {
            gemm_kernel<HID><<<(NN + 63) / 64, 256>>>(OUT, Ws + (size_t)(layer - 1) * HID * HID, Yh);
        }
        const float* lc = coeff + layer * KORD;
        const float* bptr = (layer == 0) ? b1 : (bs + (size_t)(layer - 1) * HID);
        // k=1: t_cur = prop(y); out = c0*y + c1*t_cur
        prop_kernel<0><<<PROP_BLOCKS, 256>>>(Yh, nullptr, T0h, OUT, lc, 1, rowptr, ecol, eval, nullptr);
        // Chebyshev recursion k=2..K-2
        for (int k = 2; k < KORD - 1; ++k) {
            __half* curb  = ring[(k - 1) % 3];
            __half* prevb = ring[(k - 2) % 3];
            __half* nextb = ring[k % 3];
            prop_kernel<1><<<PROP_BLOCKS, 256>>>(curb, prevb, nextb, OUT, lc, k, rowptr, ecol, eval, nullptr);
        }
        // final step k=K-1: fuse bias + relu, skip t_next store
        {
            int k = KORD - 1;
            __half* curb  = ring[(k - 1) % 3];
            __half* prevb = ring[(k - 2) % 3];
            prop_kernel<2><<<PROP_BLOCKS, 256>>>(curb, prevb, nullptr, OUT, lc, k, rowptr, ecol, eval, bptr);
        }
    }

    // global mean pool + MLP + log_softmax
    const int NCHUNK = (NN + 7) / 8;
    pool_kernel<<<(NCHUNK * HID + 255) / 256, 256>>>(OUT, batch, psum, pcnt);
    mlp_kernel<<<1, 128>>>(psum, pcnt, lin1w, lin1b, lin2w, lin2b, out);
}

// round 6
// speedup vs baseline: 1.3606x; 1.1059x over previous
#include <cuda_runtime.h>
#include <cuda_fp16.h>
#include <math.h>

#define NN 100000
#define EE 1600000
#define F_IN 128
#define HID 64
#define HEADS 8
#define KORD 14
#define NGRAPH 128
#define NCLS 10

// ---------------- scratch (static device globals; no allocs allowed) ----------------
__device__ __half g_Yh [NN * HID];   // iterate ring (fp16)
__device__ __half g_T0h[NN * HID];
__device__ __half g_T1h[NN * HID];
__device__ float  g_OUT[NN * HID];   // per-layer Chebyshev accumulator (fp32)
__device__ int    g_count [NN];
__device__ int    g_cursor[NN];
__device__ int    g_rowptr[NN + 1];
__device__ float  g_dinv  [NN];
__device__ int    g_ecol[EE];
__device__ float  g_eval[EE];
__device__ float  g_coeff[3 * KORD];
__device__ float  g_psum[NGRAPH * HID];
__device__ float  g_pcnt[NGRAPH];

// ---------------- small setup kernels ----------------
__global__ void __launch_bounds__(256) zero_kernel(int* cnt, int* cur, float* ps, float* pc) {
    int i = blockIdx.x * blockDim.x + threadIdx.x;
    if (i < NN) { cnt[i] = 0; cur[i] = 0; }
    if (i < NGRAPH * HID) ps[i] = 0.f;
    if (i < NGRAPH) pc[i] = 0.f;
}

__global__ void __launch_bounds__(64) coeff_kernel(const float* __restrict__ th1,
                             const float* __restrict__ ths,
                             float* __restrict__ gc) {
    int i = threadIdx.x;
    if (i >= 3 * KORD) return;
    int layer = i / KORD, k = i % KORD;
    const float* src = (layer == 0) ? th1 : (ths + (layer - 1) * HEADS * KORD);
    float s = 0.f;
    #pragma unroll
    for (int h = 0; h < HEADS; ++h) s += src[h * KORD + k];
    gc[i] = s * (1.0f / HEADS);
}

__global__ void __launch_bounds__(256) degree_kernel(const int* __restrict__ row, int* __restrict__ cnt) {
    int e = blockIdx.x * blockDim.x + threadIdx.x;
    if (e < EE) atomicAdd(&cnt[row[e]], 1);
}

__global__ void __launch_bounds__(256) dinv_kernel(const int* __restrict__ cnt, float* __restrict__ dinv) {
    int n = blockIdx.x * blockDim.x + threadIdx.x;
    if (n < NN) dinv[n] = rsqrtf(fmaxf((float)cnt[n], 1.0f));
}

// single-block exclusive scan over counts -> rowptr (N=100000, 1024 threads)
__global__ void __launch_bounds__(1024) scan_kernel(const int* __restrict__ cnt, int* __restrict__ rowptr) {
    __shared__ int sums[1024];
    const int CH = (NN + 1023) / 1024;  // 98
    int tid = threadIdx.x;
    int base = tid * CH;
    int s = 0;
    #pragma unroll 1
    for (int i = 0; i < CH; ++i) {
        int idx = base + i;
        if (idx < NN) s += cnt[idx];
    }
    sums[tid] = s;
    __syncthreads();
    #pragma unroll 1
    for (int off = 1; off < 1024; off <<= 1) {
        int v = (tid >= off) ? sums[tid - off] : 0;
        __syncthreads();
        sums[tid] += v;
        __syncthreads();
    }
    int run = (tid == 0) ? 0 : sums[tid - 1];
    #pragma unroll 1
    for (int i = 0; i < CH; ++i) {
        int idx = base + i;
        if (idx < NN) { rowptr[idx] = run; run += cnt[idx]; }
    }
    if (tid == 1023) rowptr[NN] = run;
}

__global__ void __launch_bounds__(256) scatter_kernel(const int* __restrict__ row, const int* __restrict__ col,
                               const float* __restrict__ dinv,
                               const int* __restrict__ rowptr, int* __restrict__ cursor,
                               int* __restrict__ ecol, float* __restrict__ eval) {
    int e = blockIdx.x * blockDim.x + threadIdx.x;
    if (e >= EE) return;
    int r = row[e], c = col[e];
    int p = rowptr[r] + atomicAdd(&cursor[r], 1);
    ecol[p] = c;
    eval[p] = dinv[r] * dinv[c];
}

// ---------------- dense y = h @ W  (F = 128 or 64, out width 64, fp16 out) ----------------
template <int F>
__global__ void __launch_bounds__(256) gemm_kernel(const float* __restrict__ x, const float* __restrict__ W,
                            __half* __restrict__ y) {
    __shared__ float sW[F * HID];
    int t = threadIdx.x;  // 256
    for (int i = t; i < F * HID; i += 256) sW[i] = W[i];
    __syncthreads();
    int rbase = blockIdx.x * 64;
    int c  = t & 63;
    int rg = t >> 6;  // 0..3
    float acc[16];
    #pragma unroll
    for (int i = 0; i < 16; ++i) acc[i] = 0.f;
    #pragma unroll 1
    for (int k = 0; k < F; ++k) {
        float w = sW[k * HID + c];
        #pragma unroll
        for (int i = 0; i < 16; ++i) {
            int r = rbase + rg + 4 * i;
            r = (r < NN) ? r : (NN - 1);
            acc[i] += x[(size_t)r * F + k] * w;
        }
    }
    #pragma unroll
    for (int i = 0; i < 16; ++i) {
        int r = rbase + rg + 4 * i;
        if (r < NN) y[(size_t)r * HID + c] = __float2half(acc[i]);
    }
}

// ---------------- sparse prop: one warp per node, CSR, wide fp16 gather ----------------
// Warp layout: 4 edge-slots (g = lane>>3) x 8 feature-lanes (sub = lane&7).
// Each lane loads a uint4 = 8 fp16 features of its slot's edge -> one LDG.128
// instruction covers 4 edges (4 independent lines in flight).
// After the edge loop: butterfly-reduce over slots; lanes with g==0 do the epilogue.
// MODE 0: t = -gather(in);          tnext = t;  out  = c0*in[row] + ck*t
// MODE 1: t = -2*gather(in) - prev; tnext = t;  out += ck*t
// MODE 2: t = -2*gather(in) - prev; out = relu(out + ck*t + bias)   (no tnext)
template <int MODE>
__global__ void __launch_bounds__(256) prop_kernel(const __half* __restrict__ in, const __half* __restrict__ tprev,
                            __half* __restrict__ tnext, float* __restrict__ out,
                            const float* __restrict__ coeff, int kidx,
                            const int* __restrict__ rowptr, const int* __restrict__ ecol,
                            const float* __restrict__ eval, const float* __restrict__ bias) {
    int warp = (blockIdx.x * blockDim.x + threadIdx.x) >> 5;
    int lane = threadIdx.x & 31;
    if (warp >= NN) return;
    int g   = lane >> 3;   // edge slot 0..3
    int sub = lane & 7;    // feature slice 0..7 (features sub*8 .. sub*8+7)
    int start = rowptr[warp];
    int end   = rowptr[warp + 1];
    float acc[8];
    #pragma unroll
    for (int i = 0; i < 8; ++i) acc[i] = 0.f;

    for (int e = start; e < end; e += 32) {
        int   myc = 0;
        float myv = 0.f;
        int idx = e + lane;
        if (idx < end) { myc = ecol[idx]; myv = eval[idx]; }
        int nsub = min(32, end - e);
        #pragma unroll
        for (int bb = 0; bb < 8; ++bb) {
            int b = bb * 4;
            if (b < nsub) {
                int   c = __shfl_sync(0xffffffffu, myc, b + g);
                float v = __shfl_sync(0xffffffffu, myv, b + g);
                if (v != 0.f) {   // invalid tail slots carry v == 0
                    const uint4* p = reinterpret_cast<const uint4*>(in + (size_t)c * HID) + sub;
                    uint4 d = *p;
                    float2 f0 = __half22float2(*reinterpret_cast<__half2*>(&d.x));
                    float2 f1 = __half22float2(*reinterpret_cast<__half2*>(&d.y));
                    float2 f2 = __half22float2(*reinterpret_cast<__half2*>(&d.z));
                    float2 f3 = __half22float2(*reinterpret_cast<__half2*>(&d.w));
                    acc[0] += v * f0.x;  acc[1] += v * f0.y;
                    acc[2] += v * f1.x;  acc[3] += v * f1.y;
                    acc[4] += v * f2.x;  acc[5] += v * f2.y;
                    acc[6] += v * f3.x;  acc[7] += v * f3.y;
                }
            }
        }
    }
    // reduce the 4 edge-slots
    #pragma unroll
    for (int i = 0; i < 8; ++i) {
        acc[i] += __shfl_xor_sync(0xffffffffu, acc[i], 8);
        acc[i] += __shfl_xor_sync(0xffffffffu, acc[i], 16);
    }
    if (g != 0) return;

    // epilogue: 8 lanes, lane sub owns features sub*8 .. sub*8+7
    float ck = coeff[kidx];
    float t[8];
    float* orow = out + (size_t)warp * HID + sub * 8;
    uint4* tnrow = reinterpret_cast<uint4*>(tnext + (size_t)warp * HID) + sub;

    if (MODE == 0) {
        #pragma unroll
        for (int i = 0; i < 8; ++i) t[i] = -acc[i];
        float c0 = coeff[0];
        uint4 yv = *(reinterpret_cast<const uint4*>(in + (size_t)warp * HID) + sub);
        float2 y0 = __half22float2(*reinterpret_cast<__half2*>(&yv.x));
        float2 y1 = __half22float2(*reinterpret_cast<__half2*>(&yv.y));
        float2 y2 = __half22float2(*reinterpret_cast<__half2*>(&yv.z));
        float2 y3 = __half22float2(*reinterpret_cast<__half2*>(&yv.w));
        float yf[8] = {y0.x, y0.y, y1.x, y1.y, y2.x, y2.y, y3.x, y3.y};
        uint4 tn;
        __half2* tnh = reinterpret_cast<__half2*>(&tn);
        #pragma unroll
        for (int i = 0; i < 4; ++i) tnh[i] = __floats2half2_rn(t[2*i], t[2*i+1]);
        *tnrow = tn;
        float4 o0, o1;
        o0.x = c0*yf[0] + ck*t[0];  o0.y = c0*yf[1] + ck*t[1];
        o0.z = c0*yf[2] + ck*t[2];  o0.w = c0*yf[3] + ck*t[3];
        o1.x = c0*yf[4] + ck*t[4];  o1.y = c0*yf[5] + ck*t[5];
        o1.z = c0*yf[6] + ck*t[6];  o1.w = c0*yf[7] + ck*t[7];
        *reinterpret_cast<float4*>(orow)     = o0;
        *reinterpret_cast<float4*>(orow + 4) = o1;
    } else {
        uint4 pv = *(reinterpret_cast<const uint4*>(tprev + (size_t)warp * HID) + sub);
        float2 p0 = __half22float2(*reinterpret_cast<__half2*>(&pv.x));
        float2 p1 = __half22float2(*reinterpret_cast<__half2*>(&pv.y));
        float2 p2 = __half22float2(*reinterpret_cast<__half2*>(&pv.z));
        float2 p3 = __half22float2(*reinterpret_cast<__half2*>(&pv.w));
        float pf[8] = {p0.x, p0.y, p1.x, p1.y, p2.x, p2.y, p3.x, p3.y};
        #pragma unroll
        for (int i = 0; i < 8; ++i) t[i] = -2.f * acc[i] - pf[i];
        float4 o0 = *reinterpret_cast<float4*>(orow);
        float4 o1 = *reinterpret_cast<float4*>(orow + 4);
        if (MODE == 1) {
            uint4 tn;
            __half2* tnh = reinterpret_cast<__half2*>(&tn);
            #pragma unroll
            for (int i = 0; i < 4; ++i) tnh[i] = __floats2half2_rn(t[2*i], t[2*i+1]);
            *tnrow = tn;
            o0.x += ck*t[0];  o0.y += ck*t[1];  o0.z += ck*t[2];  o0.w += ck*t[3];
            o1.x += ck*t[4];  o1.y += ck*t[5];  o1.z += ck*t[6];  o1.w += ck*t[7];
        } else {
            const float4 b0 = *reinterpret_cast<const float4*>(bias + sub * 8);
            const float4 b1 = *reinterpret_cast<const float4*>(bias + sub * 8 + 4);
            o0.x = fmaxf(o0.x + ck*t[0] + b0.x, 0.f);
            o0.y = fmaxf(o0.y + ck*t[1] + b0.y, 0.f);
            o0.z = fmaxf(o0.z + ck*t[2] + b0.z, 0.f);
            o0.w = fmaxf(o0.w + ck*t[3] + b0.w, 0.f);
            o1.x = fmaxf(o1.x + ck*t[4] + b1.x, 0.f);
            o1.y = fmaxf(o1.y + ck*t[5] + b1.y, 0.f);
            o1.z = fmaxf(o1.z + ck*t[6] + b1.z, 0.f);
            o1.w = fmaxf(o1.w + ck*t[7] + b1.w, 0.f);
        }
        *reinterpret_cast<float4*>(orow)     = o0;
        *reinterpret_cast<float4*>(orow + 4) = o1;
    }
}

// ---------------- pooling (batch sorted -> run-length compressed atomics) ----------------
__global__ void __launch_bounds__(256) pool_kernel(const float* __restrict__ h, const int* __restrict__ batch,
                            float* __restrict__ sums, float* __restrict__ cnts) {
    const int NCHUNK = (NN + 7) / 8;  // 12500
    int t = blockIdx.x * blockDim.x + threadIdx.x;
    if (t >= NCHUNK * HID) return;
    int f = t & 63;
    int chunk = t >> 6;
    int n0 = chunk * 8;
    int cur = -1;
    float acc = 0.f;
    #pragma unroll 1
    for (int i = 0; i < 8; ++i) {
        int n = n0 + i;
        if (n >= NN) break;
        int b = batch[n];
        if (b != cur) {
            if (cur >= 0) atomicAdd(&sums[cur * HID + f], acc);
            cur = b; acc = 0.f;
        }
        acc += h[(size_t)n * HID + f];
    }
    if (cur >= 0) atomicAdd(&sums[cur * HID + f], acc);
    if (f == 0) {
        cur = -1;
        float c = 0.f;
        #pragma unroll 1
        for (int i = 0; i < 8; ++i) {
            int n = n0 + i;
            if (n >= NN) break;
            int b = batch[n];
            if (b != cur) {
                if (cur >= 0) atomicAdd(&cnts[cur], c);
                cur = b; c = 0.f;
            }
            c += 1.f;
        }
        if (cur >= 0) atomicAdd(&cnts[cur], c);
    }
}

// ---------------- final MLP + log-softmax (one block, one thread per graph) ------------
__global__ void __launch_bounds__(128) mlp_kernel(const float* __restrict__ sums, const float* __restrict__ cnts,
                           const float* __restrict__ w1, const float* __restrict__ b1v,
                           const float* __restrict__ w2, const float* __restrict__ b2v,
                           float* __restrict__ out) {
    __shared__ float sw1[HID * HID];
    __shared__ float sb1[HID];
    __shared__ float sw2[HID * NCLS];
    __shared__ float sb2[NCLS];
    int t = threadIdx.x;
    for (int i = t; i < HID * HID; i += 128) sw1[i] = w1[i];
    for (int i = t; i < HID * NCLS; i += 128) sw2[i] = w2[i];
    if (t < HID)  sb1[t] = b1v[t];
    if (t < NCLS) sb2[t] = b2v[t];
    __syncthreads();
    if (t >= NGRAPH) return;
    float inv = 1.0f / fmaxf(cnts[t], 1.0f);
    float g[HID];
    #pragma unroll 1
    for (int i = 0; i < HID; ++i) g[i] = sums[t * HID + i] * inv;
    float hh[HID];
    #pragma unroll 1
    for (int c = 0; c < HID; ++c) {
        float s = sb1[c];
        #pragma unroll
        for (int k = 0; k < HID; ++k) s += g[k] * sw1[k * HID + c];
        hh[c] = fmaxf(s, 0.f);
    }
    float lg[NCLS];
    float mx = -1e30f;
    #pragma unroll 1
    for (int c = 0; c < NCLS; ++c) {
        float s = sb2[c];
        #pragma unroll
        for (int k = 0; k < HID; ++k) s += hh[k] * sw2[k * NCLS + c];
        lg[c] = s;
        mx = fmaxf(mx, s);
    }
    float se = 0.f;
    #pragma unroll 1
    for (int c = 0; c < NCLS; ++c) se += expf(lg[c] - mx);
    float lse = mx + logf(se);
    #pragma unroll 1
    for (int c = 0; c < NCLS; ++c) out[t * NCLS + c] = lg[c] - lse;
}

// ---------------- launch ----------------
extern "C" void kernel_launch(void* const* d_in, const int* in_sizes, int n_in,
                              void* d_out, int out_size) {
    const float* x      = (const float*)d_in[0];
    const int*   ei     = (const int*)  d_in[1];
    const int*   batch  = (const int*)  d_in[2];
    const float* W1     = (const float*)d_in[3];
    const float* theta1 = (const float*)d_in[4];
    const float* b1     = (const float*)d_in[5];
    const float* Ws     = (const float*)d_in[6];
    const float* thetas = (const float*)d_in[7];
    const float* bs     = (const float*)d_in[8];
    const float* lin1w  = (const float*)d_in[9];
    const float* lin1b  = (const float*)d_in[10];
    const float* lin2w  = (const float*)d_in[11];
    const float* lin2b  = (const float*)d_in[12];
    float* out = (float*)d_out;

    const int* row = ei;
    const int* col = ei + EE;

    __half *Yh, *T0h, *T1h;
    float *OUT, *dinv, *eval, *coeff, *psum, *pcnt;
    int *cnt, *cur, *rowptr, *ecol;
    cudaGetSymbolAddress((void**)&Yh,     g_Yh);
    cudaGetSymbolAddress((void**)&T0h,    g_T0h);
    cudaGetSymbolAddress((void**)&T1h,    g_T1h);
    cudaGetSymbolAddress((void**)&OUT,    g_OUT);
    cudaGetSymbolAddress((void**)&dinv,   g_dinv);
    cudaGetSymbolAddress((void**)&eval,   g_eval);
    cudaGetSymbolAddress((void**)&coeff,  g_coeff);
    cudaGetSymbolAddress((void**)&psum,   g_psum);
    cudaGetSymbolAddress((void**)&pcnt,   g_pcnt);
    cudaGetSymbolAddress((void**)&cnt,    g_count);
    cudaGetSymbolAddress((void**)&cur,    g_cursor);
    cudaGetSymbolAddress((void**)&rowptr, g_rowptr);
    cudaGetSymbolAddress((void**)&ecol,   g_ecol);

    // setup
    zero_kernel<<<(NN + 255) / 256, 256>>>(cnt, cur, psum, pcnt);
    coeff_kernel<<<1, 64>>>(theta1, thetas, coeff);
    degree_kernel<<<(EE + 255) / 256, 256>>>(row, cnt);
    dinv_kernel<<<(NN + 255) / 256, 256>>>(cnt, dinv);
    scan_kernel<<<1, 1024>>>(cnt, rowptr);
    scatter_kernel<<<(EE + 255) / 256, 256>>>(row, col, dinv, rowptr, cur, ecol, eval);

    const int PROP_BLOCKS = (NN * 32 + 255) / 256;
    __half* ring[3] = {Yh, T0h, T1h};

    for (int layer = 0; layer < 3; ++layer) {
        // y = h @ W  (fp16 output)
        if (layer == 0) {
            gemm_kernel<F_IN><<<(NN + 63) / 64, 256>>>(x, W1, Yh);
        } else {
            gemm_kernel<HID><<<(NN + 63) / 64, 256>>>(OUT, Ws + (size_t)(layer - 1) * HID * HID, Yh);
        }
        const float* lc = coeff + layer * KORD;
        const float* bptr = (layer == 0) ? b1 : (bs + (size_t)(layer - 1) * HID);
        // k=1: t_cur = prop(y); out = c0*y + c1*t_cur
        prop_kernel<0><<<PROP_BLOCKS, 256>>>(Yh, nullptr, T0h, OUT, lc, 1, rowptr, ecol, eval, nullptr);
        // Chebyshev recursion k=2..K-2
        for (int k = 2; k < KORD - 1; ++k) {
            __half* curb  = ring[(k - 1) % 3];
            __half* prevb = ring[(k - 2) % 3];
            __half* nextb = ring[k % 3];
            prop_kernel<1><<<PROP_BLOCKS, 256>>>(curb, prevb, nextb, OUT, lc, k, rowptr, ecol, eval, nullptr);
        }
        // final step k=K-1: fuse bias + relu, skip t_next store
        {
            int k = KORD - 1;
            __half* curb  = ring[(k - 1) % 3];
            __half* prevb = ring[(k - 2) % 3];
            prop_kernel<2><<<PROP_BLOCKS, 256>>>(curb, prevb, nullptr, OUT, lc, k, rowptr, ecol, eval, bptr);
        }
    }

    // global mean pool + MLP + log_softmax
    const int NCHUNK = (NN + 7) / 8;
    pool_kernel<<<(NCHUNK * HID + 255) / 256, 256>>>(OUT, batch, psum, pcnt);
    mlp_kernel<<<1, 128>>>(psum, pcnt, lin1w, lin1b, lin2w, lin2b, out);
}